// round 1
// baseline (speedup 1.0000x reference)
#include <cuda_runtime.h>

#define LAM 0.95f
#define ETA 0.5f
#define B_SZ 128
#define D_SZ 1024

// out[b,i,j] = LAM*A[b,i,j] + ETA*h[b,i]*h[b,j]
// Flat float4 indexing: total vec4 = B*D*D/4 = 33,554,432
// per-batch vec4 = D*D/4 = 262144 ; per-row vec4 = D/4 = 256
__global__ void __launch_bounds__(256) fastweight_kernel(
    const float4* __restrict__ A,
    const float* __restrict__ h,
    float4* __restrict__ out,
    long long n_vec4)
{
    long long idx = (long long)blockIdx.x * blockDim.x + threadIdx.x;
    long long stride = (long long)gridDim.x * blockDim.x;

    for (; idx < n_vec4; idx += stride) {
        // decompose: idx = b * 262144 + i * 256 + j4
        int b   = (int)(idx >> 18);           // / 262144
        int rem = (int)(idx & 0x3FFFF);       // % 262144
        int i   = rem >> 8;                   // / 256
        int j4  = rem & 0xFF;                 // % 256

        float hi = __ldg(&h[b * D_SZ + i]) * ETA;
        const float4 hj = __ldg(((const float4*)h) + b * (D_SZ / 4) + j4);

        float4 a = A[idx];
        float4 r;
        r.x = fmaf(hi, hj.x, a.x * LAM);
        r.y = fmaf(hi, hj.y, a.y * LAM);
        r.z = fmaf(hi, hj.z, a.z * LAM);
        r.w = fmaf(hi, hj.w, a.w * LAM);
        out[idx] = r;
    }
}

extern "C" void kernel_launch(void* const* d_in, const int* in_sizes, int n_in,
                              void* d_out, int out_size) {
    const float4* A = (const float4*)d_in[0];
    const float*  h = (const float*)d_in[1];
    float4* out = (float4*)d_out;

    long long n_vec4 = (long long)B_SZ * D_SZ * D_SZ / 4;  // 33,554,432

    // Enough blocks to saturate: 148 SMs * ~16 resident blocks of 256 thr.
    // Use a grid covering the range with modest grid-stride (1 iter per thread
    // when grid is full-size; cap grid to keep launch cheap).
    int threads = 256;
    long long blocks_ll = (n_vec4 + threads - 1) / threads;
    int blocks = (blocks_ll > 131072) ? 131072 : (int)blocks_ll;

    fastweight_kernel<<<blocks, threads>>>(A, h, out, n_vec4);
}

// round 2
// speedup vs baseline: 1.1119x; 1.1119x over previous
#include <cuda_runtime.h>

#define LAM 0.95f
#define ETA 0.5f
#define B_SZ 128
#define D_SZ 1024
#define VEC_PER_ROW (D_SZ / 4)   // 256
#define ROWS_PER_BLK 4

// out[b,i,j] = LAM*A[b,i,j] + ETA*h[b,i]*h[b,j]
// One block = ROWS_PER_BLK consecutive rows (same b). 256 threads, thread t
// owns column-group j4 = t for all 4 rows: hj loaded once, 4 A loads
// front-batched (MLP_p1=4), 4 stores. Streaming hints keep L2 clean.
__global__ void __launch_bounds__(256) fastweight_kernel(
    const float4* __restrict__ A,
    const float* __restrict__ h,
    float4* __restrict__ out)
{
    int blk = blockIdx.x;
    int b  = blk >> 6;                    // / (D_SZ/ROWS_PER_BLK/ ... ) = /64 rows-groups per batch? see below
    int rg = blk & 63;                    // row-group within batch: 1024/4 = 256 groups... fix:
    // NOTE: D_SZ/ROWS_PER_BLK = 256 row-groups per batch -> use 8 bits
    b  = blk >> 8;
    rg = blk & 255;
    int i0 = rg * ROWS_PER_BLK;
    int t  = threadIdx.x;                 // j4 in [0,256)

    long long base = ((long long)b * D_SZ + i0) * VEC_PER_ROW + t;

    // hj: resident in L1/L2 after first touch
    const float4 hj = __ldg(((const float4*)h) + b * VEC_PER_ROW + t);

    // hi for the 4 rows (uniform across the warp -> broadcast loads)
    const float* hrow = h + b * D_SZ + i0;
    float hi0 = __ldg(hrow + 0) * ETA;
    float hi1 = __ldg(hrow + 1) * ETA;
    float hi2 = __ldg(hrow + 2) * ETA;
    float hi3 = __ldg(hrow + 3) * ETA;

    // Front-batch the 4 streaming loads (MLP)
    float4 a0 = __ldcs(A + base + 0 * VEC_PER_ROW);
    float4 a1 = __ldcs(A + base + 1 * VEC_PER_ROW);
    float4 a2 = __ldcs(A + base + 2 * VEC_PER_ROW);
    float4 a3 = __ldcs(A + base + 3 * VEC_PER_ROW);

    float4 r;
    r.x = fmaf(hi0, hj.x, a0.x * LAM);
    r.y = fmaf(hi0, hj.y, a0.y * LAM);
    r.z = fmaf(hi0, hj.z, a0.z * LAM);
    r.w = fmaf(hi0, hj.w, a0.w * LAM);
    __stcs(out + base + 0 * VEC_PER_ROW, r);

    r.x = fmaf(hi1, hj.x, a1.x * LAM);
    r.y = fmaf(hi1, hj.y, a1.y * LAM);
    r.z = fmaf(hi1, hj.z, a1.z * LAM);
    r.w = fmaf(hi1, hj.w, a1.w * LAM);
    __stcs(out + base + 1 * VEC_PER_ROW, r);

    r.x = fmaf(hi2, hj.x, a2.x * LAM);
    r.y = fmaf(hi2, hj.y, a2.y * LAM);
    r.z = fmaf(hi2, hj.z, a2.z * LAM);
    r.w = fmaf(hi2, hj.w, a2.w * LAM);
    __stcs(out + base + 2 * VEC_PER_ROW, r);

    r.x = fmaf(hi3, hj.x, a3.x * LAM);
    r.y = fmaf(hi3, hj.y, a3.y * LAM);
    r.z = fmaf(hi3, hj.z, a3.z * LAM);
    r.w = fmaf(hi3, hj.w, a3.w * LAM);
    __stcs(out + base + 3 * VEC_PER_ROW, r);
}

extern "C" void kernel_launch(void* const* d_in, const int* in_sizes, int n_in,
                              void* d_out, int out_size) {
    const float4* A = (const float4*)d_in[0];
    const float*  h = (const float*)d_in[1];
    float4* out = (float4*)d_out;

    // grid = B * (D / ROWS_PER_BLK) = 128 * 256 = 32768 blocks
    int blocks = B_SZ * (D_SZ / ROWS_PER_BLK);
    fastweight_kernel<<<blocks, 256>>>(A, h, out);
}